// round 17
// baseline (speedup 1.0000x reference)
#include <cuda_runtime.h>
#include <cuda_fp16.h>
#include <math.h>
#include <stdint.h>

// Problem constants
#define BSZ   8
#define NPTS  4096
#define CDIM  128
#define KTOP  9
#define MROWS (BSZ * NPTS)   // 32768
#define EPSBN 1e-5f

// ---------------- scratch (device globals; no allocation allowed) ----------------
__device__ float g_h  [MROWS * CDIM];
__device__ float g_agg[MROWS * CDIM];
__device__ float g_t2 [MROWS * CDIM];
__device__ float g_sq [MROWS];
__device__ __half g_hh[MROWS * CDIM];   // fp16 hi split of h
__device__ __half g_hm[MROWS * CDIM];   // fp16 mid split (residual)
__device__ float g_psum[256 * 128];
__device__ float g_psq [256 * 128];
__device__ float g_mean[128];
__device__ float g_rstd[128];

// =================================================================================
// PTX helpers (baseline sm_80+ ISA only: ldmatrix / mma.sync / cp.async)
// =================================================================================
__device__ __forceinline__ uint32_t smem_u32(const void* p) {
    uint32_t a;
    asm("{ .reg .u64 t; cvta.to.shared.u64 t, %1; cvt.u32.u64 %0, t; }" : "=r"(a) : "l"(p));
    return a;
}
__device__ __forceinline__ void ldsm4(uint32_t* r, uint32_t a) {
    asm volatile("ldmatrix.sync.aligned.m8n8.x4.shared.b16 {%0,%1,%2,%3}, [%4];"
                 : "=r"(r[0]), "=r"(r[1]), "=r"(r[2]), "=r"(r[3]) : "r"(a));
}
__device__ __forceinline__ void mma16816h(float* c, const uint32_t* a, uint32_t b0, uint32_t b1) {
    asm volatile("mma.sync.aligned.m16n8k16.row.col.f32.f16.f16.f32 "
                 "{%0,%1,%2,%3},{%4,%5,%6,%7},{%8,%9},{%0,%1,%2,%3};"
                 : "+f"(c[0]), "+f"(c[1]), "+f"(c[2]), "+f"(c[3])
                 : "r"(a[0]), "r"(a[1]), "r"(a[2]), "r"(a[3]), "r"(b0), "r"(b1));
}
__device__ __forceinline__ void cp16(uint32_t dst, const void* src) {
    asm volatile("cp.async.cg.shared.global [%0], [%1], 16;" :: "r"(dst), "l"(src));
}
#define CP_COMMIT() asm volatile("cp.async.commit_group;" ::: "memory")
#define CP_WAIT(n)  asm volatile("cp.async.wait_group %0;" :: "n"(n) : "memory")

// =================================================================================
// Tiled SGEMM: out[M x 128] = A[M x 128] @ W (+ A2 @ W[128:]) + bias.
// Fused deterministic column stats (sum / sumsq) into the epilogue.
// =================================================================================
__global__ __launch_bounds__(256) void gemm128(const float* __restrict__ A,
                                               const float* __restrict__ A2,
                                               const float* __restrict__ W,
                                               const float* __restrict__ bias,
                                               float* __restrict__ out)
{
    __shared__ float As[32 * 132];
    __shared__ float Ws[32 * 132];
    const int t  = threadIdx.x;
    const int tx = t & 15, ty = t >> 4;
    const int r0 = blockIdx.x * 128;

    float c[8][8];
#pragma unroll
    for (int i = 0; i < 8; i++)
#pragma unroll
        for (int j = 0; j < 8; j++) c[i][j] = 0.f;

    const int nSrc = A2 ? 2 : 1;
    for (int si = 0; si < nSrc; si++) {
        const float* Ap = si ? A2 : A;
        const float* Wp = W + si * 128 * 128;
        for (int kc = 0; kc < 128; kc += 32) {
            __syncthreads();
#pragma unroll
            for (int i = 0; i < 4; i++) {
                int lin = t + i * 256;
                int m = lin >> 3, kq = lin & 7;
                float4 v = *(const float4*)&Ap[(size_t)(r0 + m) * 128 + kc + kq * 4];
                As[(kq * 4 + 0) * 132 + m] = v.x;
                As[(kq * 4 + 1) * 132 + m] = v.y;
                As[(kq * 4 + 2) * 132 + m] = v.z;
                As[(kq * 4 + 3) * 132 + m] = v.w;
            }
#pragma unroll
            for (int i = 0; i < 4; i++) {
                int lin = t + i * 256;
                int k = lin >> 5, n4 = lin & 31;
                float4 v = *(const float4*)&Wp[(size_t)(kc + k) * 128 + n4 * 4];
                *(float4*)&Ws[k * 132 + n4 * 4] = v;
            }
            __syncthreads();
#pragma unroll 8
            for (int k = 0; k < 32; k++) {
                float4 a0 = *(const float4*)&As[k * 132 + ty * 8];
                float4 a1 = *(const float4*)&As[k * 132 + ty * 8 + 4];
                float4 b0 = *(const float4*)&Ws[k * 132 + tx * 8];
                float4 b1 = *(const float4*)&Ws[k * 132 + tx * 8 + 4];
                float a[8] = {a0.x, a0.y, a0.z, a0.w, a1.x, a1.y, a1.z, a1.w};
                float b[8] = {b0.x, b0.y, b0.z, b0.w, b1.x, b1.y, b1.z, b1.w};
#pragma unroll
                for (int i = 0; i < 8; i++)
#pragma unroll
                    for (int j = 0; j < 8; j++) c[i][j] = fmaf(a[i], b[j], c[i][j]);
            }
        }
    }

    float bv[8];
#pragma unroll
    for (int j = 0; j < 8; j++) bv[j] = bias ? bias[tx * 8 + j] : 0.f;

    float s1[8], s2[8];
#pragma unroll
    for (int j = 0; j < 8; j++) { s1[j] = 0.f; s2[j] = 0.f; }

#pragma unroll
    for (int i = 0; i < 8; i++) {
        size_t base = (size_t)(r0 + ty * 8 + i) * 128 + tx * 8;
        float v[8];
#pragma unroll
        for (int j = 0; j < 8; j++) {
            v[j] = c[i][j] + bv[j];
            s1[j] += v[j];
            s2[j] += v[j] * v[j];
        }
        *(float4*)&out[base]     = make_float4(v[0], v[1], v[2], v[3]);
        *(float4*)&out[base + 4] = make_float4(v[4], v[5], v[6], v[7]);
    }

    __syncthreads();
#pragma unroll
    for (int j = 0; j < 8; j++) {
        As[ty * 128 + tx * 8 + j] = s1[j];
        Ws[ty * 128 + tx * 8 + j] = s2[j];
    }
    __syncthreads();
    if (t < 128) {
        float S = 0.f, Q = 0.f;
#pragma unroll
        for (int g = 0; g < 16; g++) { S += As[g * 128 + t]; Q += Ws[g * 128 + t]; }
        g_psum[blockIdx.x * 128 + t] = S;
        g_psq [blockIdx.x * 128 + t] = Q;
    }
}

__global__ void colstat_final()
{
    const int t = threadIdx.x;
    float s = 0.f, s2 = 0.f;
    for (int b = 0; b < 256; b++) { s += g_psum[b * 128 + t]; s2 += g_psq[b * 128 + t]; }
    float m   = s / (float)MROWS;
    float var = s2 / (float)MROWS - m * m;
    g_mean[t] = m;
    g_rstd[t] = rsqrtf(var + EPSBN);
}

// ============ BN apply (mode 1: +GELU, mode 2: +residual) ============
__global__ void bn_apply(const float* __restrict__ X, const float* __restrict__ gamma,
                         const float* __restrict__ beta, const float* __restrict__ resid,
                         float* __restrict__ Y, int mode)
{
    const int i4 = blockIdx.x * blockDim.x + threadIdx.x;
    const size_t i = (size_t)i4 * 4;
    const int ch = (int)(i & 127);
    float4 v  = *(const float4*)&X[i];
    float4 ga = *(const float4*)&gamma[ch];
    float4 be = *(const float4*)&beta[ch];
    float4 mn = *(const float4*)&g_mean[ch];
    float4 rs = *(const float4*)&g_rstd[ch];
    float o[4];
    o[0] = ga.x * (v.x - mn.x) * rs.x + be.x;
    o[1] = ga.y * (v.y - mn.y) * rs.y + be.y;
    o[2] = ga.z * (v.z - mn.z) * rs.z + be.z;
    o[3] = ga.w * (v.w - mn.w) * rs.w + be.w;
    if (mode == 1) {
#pragma unroll
        for (int j = 0; j < 4; j++)
            o[j] = 0.5f * o[j] * (1.f + erff(o[j] * 0.70710678118654752f));
    } else if (mode == 2) {
        float4 r = *(const float4*)&resid[i];
        o[0] += r.x; o[1] += r.y; o[2] += r.z; o[3] += r.w;
    }
    *(float4*)&Y[i] = make_float4(o[0], o[1], o[2], o[3]);
}

// ===== BN apply + fp16 2-way split + row sq-norm (fc1 output), warp per row =====
__global__ void bn_split(const float* __restrict__ X, const float* __restrict__ gamma,
                         const float* __restrict__ beta, float* __restrict__ H,
                         __half* __restrict__ Hh, __half* __restrict__ Hm,
                         float* __restrict__ sqo)
{
    const int wid = threadIdx.x >> 5, lane = threadIdx.x & 31;
    const int row = blockIdx.x * 8 + wid;
    const int ch = lane * 4;
    const size_t base = (size_t)row * 128 + ch;
    float4 v  = *(const float4*)&X[base];
    float4 ga = *(const float4*)&gamma[ch];
    float4 be = *(const float4*)&beta[ch];
    float4 mn = *(const float4*)&g_mean[ch];
    float4 rs = *(const float4*)&g_rstd[ch];
    float o[4];
    o[0] = ga.x * (v.x - mn.x) * rs.x + be.x;
    o[1] = ga.y * (v.y - mn.y) * rs.y + be.y;
    o[2] = ga.z * (v.z - mn.z) * rs.z + be.z;
    o[3] = ga.w * (v.w - mn.w) * rs.w + be.w;
    *(float4*)&H[base] = make_float4(o[0], o[1], o[2], o[3]);

    __half hh[4], hm[4];
#pragma unroll
    for (int j = 0; j < 4; j++) {
        hh[j] = __float2half_rn(o[j]);
        hm[j] = __float2half_rn(o[j] - __half2float(hh[j]));
    }
    ((__half2*)(Hh + base))[0] = __halves2half2(hh[0], hh[1]);
    ((__half2*)(Hh + base))[1] = __halves2half2(hh[2], hh[3]);
    ((__half2*)(Hm + base))[0] = __halves2half2(hm[0], hm[1]);
    ((__half2*)(Hm + base))[1] = __halves2half2(hm[2], hm[3]);

    float s = o[0]*o[0] + o[1]*o[1] + o[2]*o[2] + o[3]*o[3];
#pragma unroll
    for (int off = 16; off; off >>= 1) s += __shfl_xor_sync(0xffffffffu, s, off);
    if (lane == 0) sqo[row] = s;
}

// =================================================================================
// KNN + max-relative aggregation via mma.sync fp16 2-split (3 products).
// 256 threads, 1 CTA/SM (255-reg budget). 128 query rows/CTA; warp = 16 rows x
// FULL 64-col tile: 8 accumulators (HMMA dep distance 8). The entire A operand
// (2 splits x 8 ksteps) is register-resident for the whole kernel. Register
// top-9 lists + min-tree guard. 2-slot cp.async ring, 1 barrier per tile.
// =================================================================================
#define ROWB     272                 // padded fp16 row: 136 halves
#define QSPLIT   (128 * ROWB)        // 34816
#define QBYTES   (2 * QSPLIT)        // 69632
#define CSPLIT   (64 * ROWB)         // 17408
#define CBUF     (2 * CSPLIT)        // 34816 per ring slot
#define RING_OFF QBYTES              // 69632
#define SQN_OFF  (RING_OFF + 2 * CBUF)   // 139264 (2 slots x 256B)
#define KNN_SMEM (SQN_OFF + 512)         // 139776
#define NT       64                  // 64-cand tiles
#define TILEB    16384               // global bytes per 64-row split tile

// register insertion into sorted top-9 (strict <, stable for ascending-j feed)
#define INS9(Bst, Idx, KEY, J) do {                                        \
    float _k = (KEY); int _j = (J);                                        \
    if (_k < Bst[8]) {                                                     \
        float ck = _k; int cj = _j;                                        \
        _Pragma("unroll")                                                  \
        for (int _p = 0; _p < 9; _p++) {                                   \
            if (ck < Bst[_p]) {                                            \
                float tk = Bst[_p]; int tj = Idx[_p];                      \
                Bst[_p] = ck; Idx[_p] = cj; ck = tk; cj = tj;              \
            }                                                              \
        }                                                                  \
    }                                                                      \
} while (0)

__global__ __launch_bounds__(256, 1) void knn_mma(const __half* __restrict__ Hh,
                                                  const __half* __restrict__ Hm,
                                                  const float* __restrict__ h,
                                                  const float* __restrict__ sq,
                                                  float* __restrict__ agg)
{
    extern __shared__ __align__(16) char smp[];
    const uint32_t smb = smem_u32(smp);
    const int t = threadIdx.x, w = t >> 5, lane = t & 31;
    const int b = blockIdx.y, bOff = b * NPTS, r0 = blockIdx.x * 128;

    // strength-reduced load addressing (per-thread constants)
    const int chB  = (t & 15) * 16;             // byte offset within 256B row
    const int row0 = t >> 4;                    // 0..15
    const uint32_t dstOff = (uint32_t)(row0 * ROWB + chB);
    const size_t thrOff = (size_t)row0 * 256 + chB;

    // prologue: Q resident (128 rows x 2 splits) + tile 0 into slot 0
    {
        const char* qH = (const char*)Hh + (size_t)(bOff + r0) * 256 + thrOff;
        const char* qM = (const char*)Hm + (size_t)(bOff + r0) * 256 + thrOff;
#pragma unroll
        for (int i = 0; i < 8; i++) {
            cp16(smb + dstOff + (uint32_t)(i * 16 * ROWB), qH + i * 4096);
            cp16(smb + (uint32_t)QSPLIT + dstOff + (uint32_t)(i * 16 * ROWB), qM + i * 4096);
        }
    }
    const char* nH = (const char*)Hh + (size_t)bOff * 256 + thrOff;
    const char* nM = (const char*)Hm + (size_t)bOff * 256 + thrOff;
#pragma unroll
    for (int i = 0; i < 4; i++) {
        cp16(smb + (uint32_t)RING_OFF + dstOff + (uint32_t)(i * 16 * ROWB), nH + i * 4096);
        cp16(smb + (uint32_t)(RING_OFF + CSPLIT) + dstOff + (uint32_t)(i * 16 * ROWB), nM + i * 4096);
    }
    nH += TILEB; nM += TILEB;
    if (t < 16) cp16(smb + (uint32_t)(SQN_OFF + t * 16), (const char*)(sq + bOff) + t * 16);
    CP_COMMIT();
    CP_WAIT(0);
    __syncthreads();

    // A operand fully register-resident: [split][kstep][frag]
    uint32_t A[2][8][4];
    {
        const uint32_t aoff = (uint32_t)((w * 16 + (lane & 15)) * ROWB + ((lane >> 4) * 16));
#pragma unroll
        for (int s = 0; s < 2; s++)
#pragma unroll
            for (int ks = 0; ks < 8; ks++)
                ldsm4(A[s][ks], smb + (uint32_t)(s * QSPLIT + ks * 32) + aoff);
    }

    float bA[9], bB[9];
    int   iA[9], iB[9];
#pragma unroll
    for (int p = 0; p < 9; p++) { bA[p] = 3.0e38f; bB[p] = 3.0e38f; iA[p] = 0; iB[p] = 0; }
    float thrA = 3.0e38f, thrB = 3.0e38f;

    const uint32_t boff = (uint32_t)(((lane & 7) + ((lane & 16) ? 8 : 0)) * ROWB
                                     + ((lane & 8) ? 16 : 0));
    const int cq = 2 * (lane & 3);

    for (int ct = 0; ct < NT; ct++) {
        if (ct > 0) {
            CP_WAIT(0);        // tile ct resident
            __syncthreads();   // all warps done with tile ct-1 -> its slot is free
        }
        if (ct + 1 < NT) {
            const uint32_t pd = smb + (uint32_t)(RING_OFF + ((ct + 1) & 1) * CBUF) + dstOff;
#pragma unroll
            for (int i = 0; i < 4; i++) {
                cp16(pd + (uint32_t)(i * 16 * ROWB), nH + i * 4096);
                cp16(pd + (uint32_t)CSPLIT + (uint32_t)(i * 16 * ROWB), nM + i * 4096);
            }
            nH += TILEB; nM += TILEB;
            if (t < 16) cp16(smb + (uint32_t)(SQN_OFF + ((ct + 1) & 1) * 256 + t * 16),
                             (const char*)(sq + bOff + (ct + 1) * 64) + t * 16);
            CP_COMMIT();
        }

        const uint32_t cb = smb + (uint32_t)(RING_OFF + (ct & 1) * CBUF);

        float acc[8][4];
#pragma unroll
        for (int n8 = 0; n8 < 8; n8++)
#pragma unroll
            for (int q = 0; q < 4; q++) acc[n8][q] = 0.f;

#pragma unroll
        for (int ks = 0; ks < 8; ks++) {
            uint32_t Bh[4][4], Bm[4][4];
#pragma unroll
            for (int np = 0; np < 4; np++)
                ldsm4(Bh[np], cb + (uint32_t)(np * 16 * ROWB + ks * 32) + boff);
#pragma unroll
            for (int np = 0; np < 4; np++)
                ldsm4(Bm[np], cb + (uint32_t)(CSPLIT + np * 16 * ROWB + ks * 32) + boff);
            // hh over accs 0..7 (dep distance 8), then h*m, then m*h
#pragma unroll
            for (int np = 0; np < 4; np++) {
                mma16816h(acc[np * 2 + 0], A[0][ks], Bh[np][0], Bh[np][1]);
                mma16816h(acc[np * 2 + 1], A[0][ks], Bh[np][2], Bh[np][3]);
            }
#pragma unroll
            for (int np = 0; np < 4; np++) {
                mma16816h(acc[np * 2 + 0], A[0][ks], Bm[np][0], Bm[np][1]);
                mma16816h(acc[np * 2 + 1], A[0][ks], Bm[np][2], Bm[np][3]);
            }
#pragma unroll
            for (int np = 0; np < 4; np++) {
                mma16816h(acc[np * 2 + 0], A[1][ks], Bh[np][0], Bh[np][1]);
                mma16816h(acc[np * 2 + 1], A[1][ks], Bh[np][2], Bh[np][3]);
            }
        }

        // keys: sq[j] - 2*dot; min-tree guards the insert machinery (rare path)
        const float* sqt = (const float*)(smp + SQN_OFF + (ct & 1) * 256);
        const int jg0 = ct * 64 + cq;
        float kA[16], kB[16];
#pragma unroll
        for (int n8 = 0; n8 < 8; n8++) {
            float2 ss = *(const float2*)&sqt[n8 * 8 + cq];
            kA[n8 * 2 + 0] = fmaf(-2.f, acc[n8][0], ss.x);
            kA[n8 * 2 + 1] = fmaf(-2.f, acc[n8][1], ss.y);
            kB[n8 * 2 + 0] = fmaf(-2.f, acc[n8][2], ss.x);
            kB[n8 * 2 + 1] = fmaf(-2.f, acc[n8][3], ss.y);
        }
        float mA = kA[0], mB = kB[0];
#pragma unroll
        for (int q = 1; q < 16; q++) { mA = fminf(mA, kA[q]); mB = fminf(mB, kB[q]); }
        if (mA < thrA) {
#pragma unroll
            for (int q = 0; q < 16; q++) {
                int j = jg0 + (q >> 1) * 8 + (q & 1);
                INS9(bA, iA, kA[q], j);
            }
            thrA = bA[8];
        }
        if (mB < thrB) {
#pragma unroll
            for (int q = 0; q < 16; q++) {
                int j = jg0 + (q >> 1) * 8 + (q & 1);
                INS9(bB, iB, kB[q], j);
            }
            thrB = bB[8];
        }
    }

    // ---- merge per-row candidates: 4 contributor lanes x 9 -> top-9 per row ----
    __syncthreads();
    float* ckey = (float*)smp;                       // [128][36]
    int*   cidx = (int*)(smp + 128 * 36 * 4);        // [128][36]
    int*   nbx  = (int*)(smp + 2 * 128 * 36 * 4);    // [128][9]
    {
        const int rA = w * 16 + (lane >> 2);
        const int rB = rA + 8;
        const int sl = (lane & 3) * 9;
#pragma unroll
        for (int p = 0; p < 9; p++) {
            ckey[rA * 36 + sl + p] = bA[p];  cidx[rA * 36 + sl + p] = iA[p];
            ckey[rB * 36 + sl + p] = bB[p];  cidx[rB * 36 + sl + p] = iB[p];
        }
    }
    __syncthreads();

    if (t < 128) {
        float bk[9]; int bj[9];
#pragma unroll
        for (int p = 0; p < 9; p++) { bk[p] = 3.0e38f; bj[p] = 0x7fffffff; }
        for (int q = 0; q < 36; q++) {
            float k = ckey[t * 36 + q];
            int   j = cidx[t * 36 + q];
            if (k < bk[8] || (k == bk[8] && j < bj[8])) {
                float ck = k; int cj = j;
#pragma unroll
                for (int p = 0; p < 9; p++) {
                    if (ck < bk[p] || (ck == bk[p] && cj < bj[p])) {
                        float tk = bk[p]; int tj = bj[p];
                        bk[p] = ck; bj[p] = cj; ck = tk; cj = tj;
                    }
                }
            }
        }
#pragma unroll
        for (int p = 0; p < 9; p++) nbx[t * 9 + p] = bj[p];
    }
    __syncthreads();

    // ---- cooperative gather + max-relative aggregation (warp per 16 rows) ----
    for (int rr = 0; rr < 16; rr++) {
        const int row = w * 16 + rr;
        float4 q = *(const float4*)&h[(size_t)(bOff + r0 + row) * 128 + lane * 4];
        float m0 = -3.0e38f, m1 = -3.0e38f, m2 = -3.0e38f, m3 = -3.0e38f;
#pragma unroll
        for (int p = 0; p < KTOP; p++) {
            int j = nbx[row * 9 + p];
            float4 v = *(const float4*)&h[(size_t)(bOff + j) * 128 + lane * 4];
            m0 = fmaxf(m0, v.x); m1 = fmaxf(m1, v.y);
            m2 = fmaxf(m2, v.z); m3 = fmaxf(m3, v.w);
        }
        *(float4*)&agg[(size_t)(bOff + r0 + row) * 128 + lane * 4] =
            make_float4(m0 - q.x, m1 - q.y, m2 - q.z, m3 - q.w);
    }
}

// =================================================================================
// Launch sequence
// =================================================================================
extern "C" void kernel_launch(void* const* d_in, const int* in_sizes, int n_in,
                              void* d_out, int out_size)
{
    const float* x   = (const float*)d_in[0];
    const float* W1  = (const float*)d_in[1];
    const float* b1  = (const float*)d_in[2];
    const float* g1  = (const float*)d_in[3];
    const float* be1 = (const float*)d_in[4];
    const float* Wg  = (const float*)d_in[5];
    const float* bg  = (const float*)d_in[6];
    const float* gg  = (const float*)d_in[7];
    const float* beg = (const float*)d_in[8];
    const float* W2  = (const float*)d_in[9];
    const float* b2  = (const float*)d_in[10];
    const float* g2  = (const float*)d_in[11];
    const float* be2 = (const float*)d_in[12];
    float* out = (float*)d_out;

    float *ph, *pagg, *pt2, *psq;
    __half *phh, *phm;
    cudaGetSymbolAddress((void**)&ph,   g_h);
    cudaGetSymbolAddress((void**)&pagg, g_agg);
    cudaGetSymbolAddress((void**)&pt2,  g_t2);
    cudaGetSymbolAddress((void**)&psq,  g_sq);
    cudaGetSymbolAddress((void**)&phh,  g_hh);
    cudaGetSymbolAddress((void**)&phm,  g_hm);

    cudaFuncSetAttribute(knn_mma, cudaFuncAttributeMaxDynamicSharedMemorySize, KNN_SMEM);

    // fc1 (+fused stats) + BN/split/norms
    gemm128<<<256, 256>>>(x, nullptr, W1, b1, ph);
    colstat_final<<<1, 128>>>();
    bn_split<<<4096, 256>>>(ph, g1, be1, ph, phh, phm, psq);

    // KNN + max-relative aggregation (tensor cores via mma.sync, fp16 2-split)
    knn_mma<<<dim3(32, 8), 256, KNN_SMEM>>>(phh, phm, ph, psq, pagg);

    // graph conv MLP: cat([h, agg]) @ Wg + bg (single fused 256-K GEMM), BN, GELU
    gemm128<<<256, 256>>>(ph, pagg, Wg, bg, pt2);
    colstat_final<<<1, 128>>>();
    bn_apply<<<4096, 256>>>(pt2, gg, beg, nullptr, pt2, 1);

    // fc2 (+fused stats) + BN + residual
    gemm128<<<256, 256>>>(pt2, nullptr, W2, b2, out);
    colstat_final<<<1, 128>>>();
    bn_apply<<<4096, 256>>>(out, g2, be2, x, out, 2);
}